// round 14
// baseline (speedup 1.0000x reference)
#include <cuda_runtime.h>
#include <cuda_fp16.h>
#include <cstdint>

#define B_      1024
#define N_      4096
#define L_      8
#define K_      16
#define G_      8            // batch rows per block
#define THREADS_ 1024
#define NBLOCKS_ (B_ / G_)   // 128

// Scratch: schedule-permuted packed pairs: low 16 = index, high 16 = fp16 weight.
__device__ __align__(16) uint32_t g_pair[L_ * N_ * K_];    // 2 MB

// ---------------------------------------------------------------------------
// Sync-free per-octet gather scheduler, STATIC-priority LQF (R12 schedule,
// bit-identical picks). Lanes 0-7/8-15/... of a warp are the LDS.128
// crossbar phases; terms commute; per step the 8 lanes should hit distinct
// bank-groups (s & 7). Groups are ranked by octet-total count ONCE (SIMD-
// byte selection sort), relabeled into rank space so the per-pick rule is a
// cheap first-fit __ffs where "first" MEANS "heaviest".
// Emit buffers the 16 picked pairs in registers and stores them as
// 4 STG.128 of the thread's contiguous 64-B chunk (warp store = 512 B
// contiguous, ideal coalescing) instead of 16 stride-64B scattered stores
// (each a 32-sector wavefront) — ~8x fewer store wavefronts in prep.
// ---------------------------------------------------------------------------
__device__ __forceinline__ uint32_t bits_from_bytes(uint64_t eq) {
    // bytes 0xFF/0x00 -> 8-bit mask
    return (uint32_t)(((eq & 0x0101010101010101ull) * 0x0102040810204080ull) >> 56);
}

__global__ void prep_sched(const int* __restrict__ src,
                           const float* __restrict__ w) {
    __shared__ uint32_t buck[128 * K_];   // 8 KB: per-thread 16-pair bucket
    int gtid  = blockIdx.x * blockDim.x + threadIdx.x;
    int octet = gtid >> 3;
    int lane8 = gtid & 7;
    if (octet >= L_ * (N_ / 8)) return;
    int l = octet / (N_ / 8);
    int n = (octet % (N_ / 8)) * 8 + lane8;

    const int*   sp = src + ((size_t)l * N_ + n) * K_;
    const float* wp = w   + ((size_t)l * N_ + n) * K_;

    uint32_t pair[K_];
    uint64_t cnts = 0;
    #pragma unroll
    for (int k = 0; k < K_; k++) {
        uint32_t s16 = (uint32_t)sp[k] & 0xFFFFu;
        uint32_t w16 = (uint32_t)__half_as_ushort(__float2half_rn(wp[k]));
        pair[k] = s16 | (w16 << 16);
        cnts += 1ull << (8 * (s16 & 7));
    }
    uint64_t starts = 0;
    {
        uint32_t acc = 0;
        #pragma unroll
        for (int g = 0; g < 8; g++) {
            starts |= (uint64_t)acc << (8 * g);
            acc += (uint32_t)((cnts >> (8 * g)) & 0xFF);
        }
    }
    uint32_t base = threadIdx.x * K_;
    {
        uint64_t fill = 0;
        #pragma unroll
        for (int k = 0; k < K_; k++) {
            int g = pair[k] & 7;
            uint32_t idx = (uint32_t)((starts >> (8 * g)) & 0xFF)
                         + (uint32_t)((fill   >> (8 * g)) & 0xFF);
            fill += 1ull << (8 * g);
            buck[base + idx] = pair[k];
        }
    }

    uint64_t rem[8];
    #pragma unroll
    for (int j = 0; j < 8; j++)
        rem[j] = __shfl_sync(0xFFFFFFFFu, (unsigned long long)cnts, j, 8);

    // Octet-total per-group counts (bytes; max 128, no carry).
    uint64_t tot = 0;
    #pragma unroll
    for (int j = 0; j < 8; j++) tot += rem[j];

    // One-time priority ranking: permTab nibble r -> group id (desc count),
    // rankOf nibble g -> rank.
    uint32_t permTab = 0, rankOf = 0;
    {
        uint64_t twork = tot;
        uint32_t remg = 0xFFu;
        #pragma unroll
        for (int r = 0; r < 8; r++) {
            uint32_t lo = (uint32_t)twork, hi = (uint32_t)(twork >> 32);
            uint32_t v = __vmaxu4(lo, hi);
            v = __vmaxu4(v, v >> 16);
            v = __vmaxu4(v, v >> 8);
            uint32_t rep = (v & 0xFFu) * 0x01010101u;
            uint64_t eq = ((uint64_t)__vcmpeq4(hi, rep) << 32)
                        | (uint64_t)__vcmpeq4(lo, rep);
            uint32_t matches = bits_from_bytes(eq) & remg;
            int g = __ffs(matches) - 1;
            permTab |= (uint32_t)g << (4 * r);
            rankOf  |= (uint32_t)r << (4 * g);
            remg &= ~(1u << g);
            twork &= ~(0xFFull << (8 * g));
        }
    }

    // Availability in RANK space: bit (8*j + rank(g)).
    uint64_t availAll = 0;
    #pragma unroll
    for (int j = 0; j < 8; j++)
        #pragma unroll
        for (int g = 0; g < 8; g++)
            if ((rem[j] >> (8 * g)) & 0xFF)
                availAll |= 1ull << (8 * j + ((rankOf >> (4 * g)) & 7));

    uint64_t mypicks = 0;   // 4 bits per step (group id)
    #pragma unroll
    for (int step = 0; step < K_; step++) {
        uint32_t claimed = 0;               // rank space
        #pragma unroll
        for (int li = 0; li < 8; li++) {
            const int a = (li + step) & 7;  // rotating start lane
            uint32_t av = (uint32_t)(availAll >> (8 * a)) & 0xFFu;
            uint32_t m = av & ~claimed;
            if (!m) m = av;                 // forced collision
            int r = __ffs(m) - 1;           // lowest rank = heaviest group
            int g = (permTab >> (4 * r)) & 7;
            claimed |= 1u << r;
            rem[a] -= 1ull << (8 * g);
            if (!((rem[a] >> (8 * g)) & 0xFF))
                availAll &= ~(1ull << (8 * a + r));
            if (lane8 == a)
                mypicks |= (uint64_t)g << (4 * step);
        }
    }

    // Pop picks into registers (statically indexed), pack, store coalesced.
    uint32_t outv[K_];
    uint64_t remc = cnts;
    #pragma unroll
    for (int step = 0; step < K_; step++) {
        int g = (int)((mypicks >> (4 * step)) & 15);
        uint32_t c   = (uint32_t)((remc >> (8 * g)) & 0xFF);
        uint32_t idx = (uint32_t)((starts >> (8 * g)) & 0xFF) + c - 1;
        remc -= 1ull << (8 * g);
        outv[step] = buck[base + idx];
    }
    uint4* o4 = reinterpret_cast<uint4*>(g_pair + ((size_t)l * N_ + n) * K_);
    o4[0] = make_uint4(outv[0],  outv[1],  outv[2],  outv[3]);
    o4[1] = make_uint4(outv[4],  outv[5],  outv[6],  outv[7]);
    o4[2] = make_uint4(outv[8],  outv[9],  outv[10], outv[11]);
    o4[3] = make_uint4(outv[12], outv[13], outv[14], outv[15]);
}

// ---------------------------------------------------------------------------
// Main kernel (measured 104.6 us — unchanged). One gather index serves all
// G=8 batch rows: one LDS.128 of [s][0..7] fp16. Pairs packed
// (idx | fp16 w << 16) in schedule order.
// ---------------------------------------------------------------------------
__device__ __forceinline__ void gather_fma(const __half* __restrict__ cur,
                                           uint32_t p, float* acc) {
    uint32_t s = p & 0xFFFFu;
    float wk = __half2float(__ushort_as_half((unsigned short)(p >> 16)));
    uint4 v = *reinterpret_cast<const uint4*>(cur + s * G_);
    float2 f;
    f = __half22float2(*reinterpret_cast<__half2*>(&v.x));
    acc[0] = fmaf(f.x, wk, acc[0]); acc[1] = fmaf(f.y, wk, acc[1]);
    f = __half22float2(*reinterpret_cast<__half2*>(&v.y));
    acc[2] = fmaf(f.x, wk, acc[2]); acc[3] = fmaf(f.y, wk, acc[3]);
    f = __half22float2(*reinterpret_cast<__half2*>(&v.z));
    acc[4] = fmaf(f.x, wk, acc[4]); acc[5] = fmaf(f.y, wk, acc[5]);
    f = __half22float2(*reinterpret_cast<__half2*>(&v.w));
    acc[6] = fmaf(f.x, wk, acc[6]); acc[7] = fmaf(f.y, wk, acc[7]);
}

__global__ void __launch_bounds__(THREADS_, 1)
genome_kernel(const float* __restrict__ x, float* __restrict__ out) {
    extern __shared__ __half sm[];
    __half* bufA = sm;               // [N_][G_]
    __half* bufB = sm + N_ * G_;     // double buffer
    const int b0 = blockIdx.x * G_;

    for (int n = threadIdx.x; n < N_; n += THREADS_) {
        __half tmp[G_];
        #pragma unroll
        for (int g = 0; g < G_; g++)
            tmp[g] = __float2half_rn(x[(size_t)(b0 + g) * N_ + n]);
        *reinterpret_cast<uint4*>(bufA + (size_t)n * G_) =
            *reinterpret_cast<uint4*>(tmp);
    }
    __syncthreads();

    #pragma unroll 1
    for (int l = 0; l < L_; l++) {
        const __half* cur = (l & 1) ? bufB : bufA;
        __half*       nxt = (l & 1) ? bufA : bufB;
        const uint4*  pv  = reinterpret_cast<const uint4*>(g_pair) + (size_t)l * N_ * 4;
        const bool last = (l == L_ - 1);

        #pragma unroll 1
        for (int n = threadIdx.x; n < N_; n += THREADS_) {
            float acc[G_];
            #pragma unroll
            for (int g = 0; g < G_; g++) acc[g] = 0.0f;

            #pragma unroll
            for (int q = 0; q < 4; q++) {           // 4 pairs per uint4
                uint4 p = pv[n * 4 + q];
                gather_fma(cur, p.x, acc);
                gather_fma(cur, p.y, acc);
                gather_fma(cur, p.z, acc);
                gather_fma(cur, p.w, acc);
            }

            float r[G_];
            #pragma unroll
            for (int g = 0; g < G_; g++)
                asm("tanh.approx.f32 %0, %1;" : "=f"(r[g]) : "f"(acc[g]));

            if (!last) {
                __half2 p[G_ / 2];
                #pragma unroll
                for (int g = 0; g < G_ / 2; g++)
                    p[g] = __floats2half2_rn(r[2 * g], r[2 * g + 1]);
                *reinterpret_cast<uint4*>(nxt + (size_t)n * G_) =
                    *reinterpret_cast<const uint4*>(p);
            } else {
                #pragma unroll
                for (int g = 0; g < G_; g++)
                    out[(size_t)(b0 + g) * N_ + n] = r[g];
            }
        }
        __syncthreads();
    }
}

extern "C" void kernel_launch(void* const* d_in, const int* in_sizes, int n_in,
                              void* d_out, int out_size) {
    const float* x   = (const float*)d_in[0];
    const int*   src = (const int*)d_in[1];
    const float* w   = (const float*)d_in[2];
    float*       out = (float*)d_out;

    int total = L_ * N_;   // 8 threads per octet
    prep_sched<<<(total + 127) / 128, 128>>>(src, w);

    size_t smem = (size_t)2 * N_ * G_ * sizeof(__half);  // 128 KB
    cudaFuncSetAttribute(genome_kernel,
                         cudaFuncAttributeMaxDynamicSharedMemorySize, (int)smem);
    genome_kernel<<<NBLOCKS_, THREADS_, smem>>>(x, out);
}

// round 15
// speedup vs baseline: 1.0178x; 1.0178x over previous
#include <cuda_runtime.h>
#include <cuda_fp16.h>
#include <cstdint>

#define B_      1024
#define N_      4096
#define L_      8
#define K_      16
#define G_      8            // batch rows per block
#define THREADS_ 1024
#define NBLOCKS_ (B_ / G_)   // 128

// Scratch: schedule-permuted packed pairs: low 16 = index, high 16 = fp16 weight.
__device__ __align__(16) uint32_t g_pair[L_ * N_ * K_];    // 2 MB

// ---------------------------------------------------------------------------
// Sync-free per-octet gather scheduler, STATIC-priority LQF, RANK-SPACE.
// Lanes 0-7/8-15/... of a warp are the LDS.128 crossbar phases; terms
// commute; per step the 8 lanes should hit distinct bank-groups (s & 7).
// Groups are ranked by octet-total count ONCE (SIMD-byte selection sort).
// R15 change: everything downstream runs in RANK space — pairs are bucket-
// sorted by rank, count vectors converted to rank order before the octet
// shuffle — so the 128-pick unrolled loop needs no rank->group translation
// (picks ARE ranks) and emit pops ranks directly. Pick sequence is
// bit-identical to R12/R14 (same ffs on the same masks); only prep's
// instruction count / I$ footprint shrinks.
// ---------------------------------------------------------------------------
__device__ __forceinline__ uint32_t bits_from_bytes(uint64_t eq) {
    // bytes 0xFF/0x00 -> 8-bit mask
    return (uint32_t)(((eq & 0x0101010101010101ull) * 0x0102040810204080ull) >> 56);
}

__global__ void prep_sched(const int* __restrict__ src,
                           const float* __restrict__ w) {
    __shared__ uint32_t buck[128 * K_];   // 8 KB: per-thread 16-pair bucket
    int gtid  = blockIdx.x * blockDim.x + threadIdx.x;
    int octet = gtid >> 3;
    int lane8 = gtid & 7;
    if (octet >= L_ * (N_ / 8)) return;
    int l = octet / (N_ / 8);
    int n = (octet % (N_ / 8)) * 8 + lane8;

    const int*   sp = src + ((size_t)l * N_ + n) * K_;
    const float* wp = w   + ((size_t)l * N_ + n) * K_;

    // Pack pairs + per-group counts (8 groups x 8-bit bytes of a uint64).
    uint32_t pair[K_];
    uint64_t cnts = 0;
    #pragma unroll
    for (int k = 0; k < K_; k++) {
        uint32_t s16 = (uint32_t)sp[k] & 0xFFFFu;
        uint32_t w16 = (uint32_t)__half_as_ushort(__float2half_rn(wp[k]));
        pair[k] = s16 | (w16 << 16);
        cnts += 1ull << (8 * (s16 & 7));
    }

    // Octet totals (group space) for ranking.
    uint64_t tot = 0;
    #pragma unroll
    for (int j = 0; j < 8; j++)
        tot += __shfl_sync(0xFFFFFFFFu, (unsigned long long)cnts, j, 8);

    // One-time priority ranking: permTab nibble r -> group id (desc count),
    // rankOf nibble g -> rank.
    uint32_t permTab = 0, rankOf = 0;
    {
        uint64_t twork = tot;
        uint32_t remg = 0xFFu;
        #pragma unroll
        for (int r = 0; r < 8; r++) {
            uint32_t lo = (uint32_t)twork, hi = (uint32_t)(twork >> 32);
            uint32_t v = __vmaxu4(lo, hi);
            v = __vmaxu4(v, v >> 16);
            v = __vmaxu4(v, v >> 8);
            uint32_t rep = (v & 0xFFu) * 0x01010101u;
            uint64_t eq = ((uint64_t)__vcmpeq4(hi, rep) << 32)
                        | (uint64_t)__vcmpeq4(lo, rep);
            uint32_t matches = bits_from_bytes(eq) & remg;
            int g = __ffs(matches) - 1;
            permTab |= (uint32_t)g << (4 * r);
            rankOf  |= (uint32_t)r << (4 * g);
            remg &= ~(1u << g);
            twork &= ~(0xFFull << (8 * g));
        }
    }

    // Convert own counts to rank space: byte r of rcnts = byte permTab[r] of cnts.
    uint64_t rcnts = 0;
    #pragma unroll
    for (int r = 0; r < 8; r++) {
        int g = (permTab >> (4 * r)) & 7;
        rcnts |= ((cnts >> (8 * g)) & 0xFF) << (8 * r);
    }
    // Rank-space exclusive prefix (bucket starts).
    uint64_t rstarts = 0;
    {
        uint32_t acc = 0;
        #pragma unroll
        for (int r = 0; r < 8; r++) {
            rstarts |= (uint64_t)acc << (8 * r);
            acc += (uint32_t)((rcnts >> (8 * r)) & 0xFF);
        }
    }
    // Counting-sort pairs into the shared bucket, ordered by RANK.
    uint32_t base = threadIdx.x * K_;
    {
        uint64_t fill = 0;
        #pragma unroll
        for (int k = 0; k < K_; k++) {
            int r = (rankOf >> (4 * (pair[k] & 7))) & 7;
            uint32_t idx = (uint32_t)((rstarts >> (8 * r)) & 0xFF)
                         + (uint32_t)((fill    >> (8 * r)) & 0xFF);
            fill += 1ull << (8 * r);
            buck[base + idx] = pair[k];
        }
    }

    // Exchange RANK-space count vectors across the octet.
    uint64_t rem[8];
    #pragma unroll
    for (int j = 0; j < 8; j++)
        rem[j] = __shfl_sync(0xFFFFFFFFu, (unsigned long long)rcnts, j, 8);

    // availAll: bit (8*j + r) set iff lane j still has pairs at rank r.
    uint64_t availAll = 0;
    #pragma unroll
    for (int j = 0; j < 8; j++)
        #pragma unroll
        for (int r = 0; r < 8; r++)
            if ((rem[j] >> (8 * r)) & 0xFF) availAll |= 1ull << (8 * j + r);

    // Greedy: per step, rotating start lane; each pick = first-fit __ffs in
    // rank space (lowest rank = heaviest group). No translation in the loop.
    uint64_t mypicks = 0;   // 4 bits per step (rank)
    #pragma unroll
    for (int step = 0; step < K_; step++) {
        uint32_t claimed = 0;
        #pragma unroll
        for (int li = 0; li < 8; li++) {
            const int a = (li + step) & 7;  // compile-time
            uint32_t av = (uint32_t)(availAll >> (8 * a)) & 0xFFu;
            uint32_t m = av & ~claimed;
            if (!m) m = av;                 // forced collision
            int r = __ffs(m) - 1;
            claimed |= 1u << r;
            rem[a] -= 1ull << (8 * r);
            if (!((rem[a] >> (8 * r)) & 0xFF))
                availAll &= ~(1ull << (8 * a + r));
            if (lane8 == a)
                mypicks |= (uint64_t)r << (4 * step);
        }
    }

    // Pop picks (rank space) into registers, pack, store coalesced.
    uint32_t outv[K_];
    uint64_t remc = rcnts;
    #pragma unroll
    for (int step = 0; step < K_; step++) {
        int r = (int)((mypicks >> (4 * step)) & 15);
        uint32_t c   = (uint32_t)((remc >> (8 * r)) & 0xFF);
        uint32_t idx = (uint32_t)((rstarts >> (8 * r)) & 0xFF) + c - 1;
        remc -= 1ull << (8 * r);
        outv[step] = buck[base + idx];
    }
    uint4* o4 = reinterpret_cast<uint4*>(g_pair + ((size_t)l * N_ + n) * K_);
    o4[0] = make_uint4(outv[0],  outv[1],  outv[2],  outv[3]);
    o4[1] = make_uint4(outv[4],  outv[5],  outv[6],  outv[7]);
    o4[2] = make_uint4(outv[8],  outv[9],  outv[10], outv[11]);
    o4[3] = make_uint4(outv[12], outv[13], outv[14], outv[15]);
}

// ---------------------------------------------------------------------------
// Main kernel (measured best — unchanged). One gather index serves all G=8
// batch rows: one LDS.128 of [s][0..7] fp16. Pairs packed
// (idx | fp16 w << 16) in schedule order.
// ---------------------------------------------------------------------------
__device__ __forceinline__ void gather_fma(const __half* __restrict__ cur,
                                           uint32_t p, float* acc) {
    uint32_t s = p & 0xFFFFu;
    float wk = __half2float(__ushort_as_half((unsigned short)(p >> 16)));
    uint4 v = *reinterpret_cast<const uint4*>(cur + s * G_);
    float2 f;
    f = __half22float2(*reinterpret_cast<__half2*>(&v.x));
    acc[0] = fmaf(f.x, wk, acc[0]); acc[1] = fmaf(f.y, wk, acc[1]);
    f = __half22float2(*reinterpret_cast<__half2*>(&v.y));
    acc[2] = fmaf(f.x, wk, acc[2]); acc[3] = fmaf(f.y, wk, acc[3]);
    f = __half22float2(*reinterpret_cast<__half2*>(&v.z));
    acc[4] = fmaf(f.x, wk, acc[4]); acc[5] = fmaf(f.y, wk, acc[5]);
    f = __half22float2(*reinterpret_cast<__half2*>(&v.w));
    acc[6] = fmaf(f.x, wk, acc[6]); acc[7] = fmaf(f.y, wk, acc[7]);
}

__global__ void __launch_bounds__(THREADS_, 1)
genome_kernel(const float* __restrict__ x, float* __restrict__ out) {
    extern __shared__ __half sm[];
    __half* bufA = sm;               // [N_][G_]
    __half* bufB = sm + N_ * G_;     // double buffer
    const int b0 = blockIdx.x * G_;

    for (int n = threadIdx.x; n < N_; n += THREADS_) {
        __half tmp[G_];
        #pragma unroll
        for (int g = 0; g < G_; g++)
            tmp[g] = __float2half_rn(x[(size_t)(b0 + g) * N_ + n]);
        *reinterpret_cast<uint4*>(bufA + (size_t)n * G_) =
            *reinterpret_cast<uint4*>(tmp);
    }
    __syncthreads();

    #pragma unroll 1
    for (int l = 0; l < L_; l++) {
        const __half* cur = (l & 1) ? bufB : bufA;
        __half*       nxt = (l & 1) ? bufA : bufB;
        const uint4*  pv  = reinterpret_cast<const uint4*>(g_pair) + (size_t)l * N_ * 4;
        const bool last = (l == L_ - 1);

        #pragma unroll 1
        for (int n = threadIdx.x; n < N_; n += THREADS_) {
            float acc[G_];
            #pragma unroll
            for (int g = 0; g < G_; g++) acc[g] = 0.0f;

            #pragma unroll
            for (int q = 0; q < 4; q++) {           // 4 pairs per uint4
                uint4 p = pv[n * 4 + q];
                gather_fma(cur, p.x, acc);
                gather_fma(cur, p.y, acc);
                gather_fma(cur, p.z, acc);
                gather_fma(cur, p.w, acc);
            }

            float r[G_];
            #pragma unroll
            for (int g = 0; g < G_; g++)
                asm("tanh.approx.f32 %0, %1;" : "=f"(r[g]) : "f"(acc[g]));

            if (!last) {
                __half2 p[G_ / 2];
                #pragma unroll
                for (int g = 0; g < G_ / 2; g++)
                    p[g] = __floats2half2_rn(r[2 * g], r[2 * g + 1]);
                *reinterpret_cast<uint4*>(nxt + (size_t)n * G_) =
                    *reinterpret_cast<const uint4*>(p);
            } else {
                #pragma unroll
                for (int g = 0; g < G_; g++)
                    out[(size_t)(b0 + g) * N_ + n] = r[g];
            }
        }
        __syncthreads();
    }
}

extern "C" void kernel_launch(void* const* d_in, const int* in_sizes, int n_in,
                              void* d_out, int out_size) {
    const float* x   = (const float*)d_in[0];
    const int*   src = (const int*)d_in[1];
    const float* w   = (const float*)d_in[2];
    float*       out = (float*)d_out;

    int total = L_ * N_;   // 8 threads per octet
    prep_sched<<<(total + 127) / 128, 128>>>(src, w);

    size_t smem = (size_t)2 * N_ * G_ * sizeof(__half);  // 128 KB
    cudaFuncSetAttribute(genome_kernel,
                         cudaFuncAttributeMaxDynamicSharedMemorySize, (int)smem);
    genome_kernel<<<NBLOCKS_, THREADS_, smem>>>(x, out);
}